// round 3
// baseline (speedup 1.0000x reference)
#include <cuda_runtime.h>

#define N_NODES 255
#define NNZ_E   2550
#define BATCH   512
#define M_ROWS  (BATCH * N_NODES)   // 130560 (divisible by 256)
#define MAXD    400

// ---------------- device scratch (no allocations allowed) ----------------
__device__ float g_bufA[M_ROWS * MAXD];
__device__ float g_bufB[M_ROWS * MAXD];
__device__ int   g_rowptr[2][N_NODES + 1];
__device__ int   g_cols[2][NNZ_E];
__device__ float g_vals[2][NNZ_E];
__device__ float g_rowsum[2][N_NODES];

// ---------------- deterministic COO -> CSR build (1 block per matrix) ----
__global__ void build_csr_kernel(const int* __restrict__ sm_idx, const float* __restrict__ sm_val,
                                 const int* __restrict__ sp_idx, const float* __restrict__ sp_val) {
    __shared__ int   srow[NNZ_E];
    __shared__ float sval[NNZ_E];
    __shared__ int   rptr[N_NODES + 1];
    __shared__ int   cnt[N_NODES];
    const int mat = blockIdx.x;
    const int*   idx = mat ? sp_idx : sm_idx;
    const float* val = mat ? sp_val : sm_val;
    const int t = threadIdx.x;

    for (int e = t; e < NNZ_E; e += blockDim.x) { srow[e] = idx[2 * e]; sval[e] = val[e]; }
    for (int i = t; i < N_NODES; i += blockDim.x) cnt[i] = 0;
    __syncthreads();
    for (int e = t; e < NNZ_E; e += blockDim.x) atomicAdd(&cnt[srow[e]], 1);
    __syncthreads();
    if (t == 0) {
        int s = 0;
        for (int i = 0; i < N_NODES; i++) { rptr[i] = s; s += cnt[i]; }
        rptr[N_NODES] = s;
    }
    __syncthreads();
    // rank within row by original edge order -> fully deterministic CSR
    for (int e = t; e < NNZ_E; e += blockDim.x) {
        const int r = srow[e];
        int rank = 0;
        for (int e2 = 0; e2 < e; e2++) rank += (srow[e2] == r) ? 1 : 0;
        const int slot = rptr[r] + rank;
        g_cols[mat][slot] = idx[2 * e + 1];
        g_vals[mat][slot] = sval[e];
    }
    for (int i = t; i <= N_NODES; i += blockDim.x) g_rowptr[mat][i] = rptr[i];
    for (int i = t; i < N_NODES; i += blockDim.x) {
        float s = 0.f;
        for (int e = 0; e < NNZ_E; e++)
            if (srow[e] == i) s += sval[e];
        g_rowsum[mat][i] = s;
    }
}

// ---------------- SpMM, feature dim = 2 (thread per (b,i)) ---------------
__global__ void spmm_d2_kernel(int mat, const float* __restrict__ X,
                               float* __restrict__ out, int relu) {
    const int t = blockIdx.x * blockDim.x + threadIdx.x;
    if (t >= M_ROWS) return;
    const int b = t / N_NODES;
    const int i = t - b * N_NODES;
    const int p0 = g_rowptr[mat][i], p1 = g_rowptr[mat][i + 1];
    const float2* Xb = reinterpret_cast<const float2*>(X) + (size_t)b * N_NODES;
    float a0 = 0.f, a1 = 0.f;
    for (int e = p0; e < p1; e++) {
        const float v = g_vals[mat][e];
        const float2 x = Xb[g_cols[mat][e]];
        a0 = fmaf(v, x.x, a0);
        a1 = fmaf(v, x.y, a1);
    }
    if (relu) { a0 = fmaxf(a0, 0.f); a1 = fmaxf(a1, 0.f); }
    reinterpret_cast<float2*>(out)[t] = make_float2(a0, a1);
}

// ---------------- SpMM, generic d (d % 4 == 0), block per (i, b) ---------
__global__ void spmm_kernel(int mat, const float* __restrict__ Z,
                            float* __restrict__ out, int d, int relu) {
    const int i = blockIdx.x, b = blockIdx.y;
    const int p0 = g_rowptr[mat][i], p1 = g_rowptr[mat][i + 1];
    const float* Zb = Z + (size_t)b * N_NODES * d;
    float* ob = out + ((size_t)b * N_NODES + i) * d;
    const int d4 = d >> 2;
    for (int q = threadIdx.x; q < d4; q += blockDim.x) {
        float4 acc = make_float4(0.f, 0.f, 0.f, 0.f);
        for (int e = p0; e < p1; e++) {
            const float v = g_vals[mat][e];
            const float4 z = *reinterpret_cast<const float4*>(Zb + g_cols[mat][e] * d + q * 4);
            acc.x = fmaf(v, z.x, acc.x);
            acc.y = fmaf(v, z.y, acc.y);
            acc.z = fmaf(v, z.z, acc.z);
            acc.w = fmaf(v, z.w, acc.w);
        }
        if (relu) {
            acc.x = fmaxf(acc.x, 0.f); acc.y = fmaxf(acc.y, 0.f);
            acc.z = fmaxf(acc.z, 0.f); acc.w = fmaxf(acc.w, 0.f);
        }
        *reinterpret_cast<float4*>(ob + q * 4) = acc;
    }
}

// ---------------- main GEMM: C = act(A @ W + scale*bias) -----------------
// MODE 0: C = A@W + bias
// MODE 1: C = relu(A@W + rowsum[m%255]*bias)
// fp32 via packed fma.rn.f32x2. A stored SCALAR in smem, duplicated into
// f32x2 pair lanes in registers (mov.b64 {f,f}) -> halves LDS bytes/FLOP.
// 16x8 per-thread tile, BM=256/BN=128/BK=16, double-buffered smem.
#define BM 256
#define BN 128
#define BK 16

typedef unsigned long long u64;

__device__ __forceinline__ void ffma2(u64& d, u64 a, u64 b) {
    asm("fma.rn.f32x2 %0, %1, %2, %0;" : "+l"(d) : "l"(a), "l"(b));
}
__device__ __forceinline__ u64 dup2(float f) {
    u64 r;
    asm("mov.b64 %0, {%1, %1};" : "=l"(r) : "f"(f));
    return r;
}

template <int MODE>
__global__ __launch_bounds__(256, 1)
void gemm_kernel(const float* __restrict__ A, const float* __restrict__ Wt,
                 const float* __restrict__ bias, int mat,
                 float* __restrict__ C, int K, int N) {
    __shared__ float As[2][BK][BM];  // 32 KB
    __shared__ float Bs[2][BK][BN];  // 16 KB

    const int tid = threadIdx.x;
    const int mBase = blockIdx.x * BM;
    const int nBase = blockIdx.y * BN;
    const int tr = (tid >> 4) << 4;   // 0..240, 16 rows/thread
    const int tc = (tid & 15) << 3;   // 0..120, 8 cols/thread

    u64 acc[16][4];
#pragma unroll
    for (int i = 0; i < 16; i++)
#pragma unroll
        for (int j = 0; j < 4; j++) acc[i][j] = 0ull;

    const float* Arow = A + (size_t)(mBase + tid) * K;  // thread loads 1 full A row slab
    const int brow = tid >> 4;          // 0..15
    const int bcol = (tid & 15) << 3;   // 0..120
    const bool bcolok0 = (nBase + bcol) < N;       // float4 valid (N%4==0)
    const bool bcolok1 = (nBase + bcol + 4) < N;

    const int ntiles = (K + BK - 1) / BK;
    float4 aS[4], bS[2];
    const float4 fz = make_float4(0.f, 0.f, 0.f, 0.f);

    // --- prefetch tile 0 ---
    {
        const int k0 = 0;
#pragma unroll
        for (int q = 0; q < 4; q++) {
            const int k = k0 + 4 * q;
            aS[q] = (k < K) ? *reinterpret_cast<const float4*>(Arow + k) : fz;
        }
        const int kr = k0 + brow;
        const float* Brow = Wt + (size_t)kr * N + nBase;
        const bool okk = kr < K;
        bS[0] = (okk && bcolok0) ? *reinterpret_cast<const float4*>(Brow + bcol) : fz;
        bS[1] = (okk && bcolok1) ? *reinterpret_cast<const float4*>(Brow + bcol + 4) : fz;
    }
    // store tile 0 -> buf 0
    {
#pragma unroll
        for (int q = 0; q < 4; q++) {
            As[0][4 * q + 0][tid] = aS[q].x;
            As[0][4 * q + 1][tid] = aS[q].y;
            As[0][4 * q + 2][tid] = aS[q].z;
            As[0][4 * q + 3][tid] = aS[q].w;
        }
        *reinterpret_cast<float4*>(&Bs[0][brow][bcol])     = bS[0];
        *reinterpret_cast<float4*>(&Bs[0][brow][bcol + 4]) = bS[1];
    }
    __syncthreads();

    for (int it = 0; it < ntiles; it++) {
        const int p = it & 1;
        if (it + 1 < ntiles) {
            const int k0 = (it + 1) * BK;
#pragma unroll
            for (int q = 0; q < 4; q++) {
                const int k = k0 + 4 * q;
                aS[q] = (k < K) ? *reinterpret_cast<const float4*>(Arow + k) : fz;
            }
            const int kr = k0 + brow;
            const float* Brow = Wt + (size_t)kr * N + nBase;
            const bool okk = kr < K;
            bS[0] = (okk && bcolok0) ? *reinterpret_cast<const float4*>(Brow + bcol) : fz;
            bS[1] = (okk && bcolok1) ? *reinterpret_cast<const float4*>(Brow + bcol + 4) : fz;
        }

        // compute from buffer p
#pragma unroll 4
        for (int kk = 0; kk < BK; kk++) {
            const float4 a0 = *reinterpret_cast<const float4*>(&As[p][kk][tr]);
            const float4 a1 = *reinterpret_cast<const float4*>(&As[p][kk][tr + 4]);
            const float4 a2 = *reinterpret_cast<const float4*>(&As[p][kk][tr + 8]);
            const float4 a3 = *reinterpret_cast<const float4*>(&As[p][kk][tr + 12]);
            const ulonglong2 bq0 = *reinterpret_cast<const ulonglong2*>(&Bs[p][kk][tc]);
            const ulonglong2 bq1 = *reinterpret_cast<const ulonglong2*>(&Bs[p][kk][tc + 4]);
            const float af[16] = {a0.x, a0.y, a0.z, a0.w, a1.x, a1.y, a1.z, a1.w,
                                  a2.x, a2.y, a2.z, a2.w, a3.x, a3.y, a3.z, a3.w};
#pragma unroll
            for (int i = 0; i < 16; i++) {
                const u64 ad = dup2(af[i]);
                ffma2(acc[i][0], ad, bq0.x);
                ffma2(acc[i][1], ad, bq0.y);
                ffma2(acc[i][2], ad, bq1.x);
                ffma2(acc[i][3], ad, bq1.y);
            }
        }

        if (it + 1 < ntiles) {
            const int pn = (it + 1) & 1;
#pragma unroll
            for (int q = 0; q < 4; q++) {
                As[pn][4 * q + 0][tid] = aS[q].x;
                As[pn][4 * q + 1][tid] = aS[q].y;
                As[pn][4 * q + 2][tid] = aS[q].z;
                As[pn][4 * q + 3][tid] = aS[q].w;
            }
            *reinterpret_cast<float4*>(&Bs[pn][brow][bcol])     = bS[0];
            *reinterpret_cast<float4*>(&Bs[pn][brow][bcol + 4]) = bS[1];
            __syncthreads();
        }
    }

    // epilogue
    float bcols[8];
#pragma unroll
    for (int j = 0; j < 8; j++) {
        const int n = nBase + tc + j;
        bcols[j] = (n < N) ? bias[n] : 0.f;
    }
#pragma unroll
    for (int i = 0; i < 16; i++) {
        const int m = mBase + tr + i;
        float sc = 1.f;
        if (MODE == 1) sc = g_rowsum[mat][m % N_NODES];
        float outv[8];
#pragma unroll
        for (int j = 0; j < 4; j++) {
            const float2 pp = *reinterpret_cast<float2*>(&acc[i][j]);
            outv[2 * j]     = pp.x + bcols[2 * j] * sc;
            outv[2 * j + 1] = pp.y + bcols[2 * j + 1] * sc;
        }
        if (MODE == 1) {
#pragma unroll
            for (int j = 0; j < 8; j++) outv[j] = fmaxf(outv[j], 0.f);
        }
        float* crow = C + (size_t)m * N + nBase + tc;
        if (nBase + tc < N)
            *reinterpret_cast<float4*>(crow) =
                make_float4(outv[0], outv[1], outv[2], outv[3]);
        if (nBase + tc + 4 < N)
            *reinterpret_cast<float4*>(crow + 4) =
                make_float4(outv[4], outv[5], outv[6], outv[7]);
    }
}

// ---------------- enc0: out = relu( x0*W[0,:] + x1*W[1,:] + rowsum*b ) ---
// (replaces the K=2 GEMM; pure HBM-write bound)
__global__ void enc0_kernel(const float* __restrict__ X2, const float* __restrict__ W,
                            const float* __restrict__ b, float* __restrict__ out) {
    const int idx = blockIdx.x * blockDim.x + threadIdx.x;  // over M_ROWS*100 float4s
    if (idx >= M_ROWS * 100) return;
    const int m = idx / 100;
    const int q = idx - m * 100;
    const float2 a = reinterpret_cast<const float2*>(X2)[m];
    const float4 w0 = reinterpret_cast<const float4*>(W)[q];
    const float4 w1 = reinterpret_cast<const float4*>(W + 400)[q];
    const float4 bv = reinterpret_cast<const float4*>(b)[q];
    const float sc = g_rowsum[0][m % N_NODES];
    float4 o;
    o.x = fmaxf(fmaf(a.x, w0.x, fmaf(a.y, w1.x, sc * bv.x)), 0.f);
    o.y = fmaxf(fmaf(a.x, w0.y, fmaf(a.y, w1.y, sc * bv.y)), 0.f);
    o.z = fmaxf(fmaf(a.x, w0.z, fmaf(a.y, w1.z, sc * bv.z)), 0.f);
    o.w = fmaxf(fmaf(a.x, w0.w, fmaf(a.y, w1.w, sc * bv.w)), 0.f);
    reinterpret_cast<float4*>(out)[idx] = o;
}

// ---------------- thin GEMM for N=2 (dec2): warp per row -----------------
__global__ void gemm_thin_kernel(const float* __restrict__ X, const float* __restrict__ Wt,
                                 const float* __restrict__ bias, float* __restrict__ out, int K) {
    __shared__ float Ws[2 * MAXD];
    for (int i = threadIdx.x; i < 2 * K; i += blockDim.x) Ws[i] = Wt[i];
    __syncthreads();
    const int warp = threadIdx.x >> 5, lane = threadIdx.x & 31;
    const int row = blockIdx.x * 8 + warp;
    if (row >= M_ROWS) return;
    const float* x = X + (size_t)row * K;
    float a0 = 0.f, a1 = 0.f;
    for (int k = lane; k < K; k += 32) {
        const float xv = x[k];
        a0 = fmaf(xv, Ws[2 * k], a0);
        a1 = fmaf(xv, Ws[2 * k + 1], a1);
    }
#pragma unroll
    for (int off = 16; off; off >>= 1) {
        a0 += __shfl_down_sync(0xffffffffu, a0, off);
        a1 += __shfl_down_sync(0xffffffffu, a1, off);
    }
    if (lane == 0) {
        out[2 * row]     = a0 + bias[0];
        out[2 * row + 1] = a1 + bias[1];
    }
}

// ---------------- launch -------------------------------------------------
static inline int spmm_threads(int d) {
    int t = ((d >> 2) + 31) & ~31;
    if (t < 32) t = 32;
    if (t > 128) t = 128;
    return t;
}

extern "C" void kernel_launch(void* const* d_in, const int* in_sizes, int n_in,
                              void* d_out, int out_size) {
    const float* H   = (const float*)d_in[0];
    const float* smv = (const float*)d_in[1];
    const float* spv = (const float*)d_in[2];
    const float* W[6];
    const float* bb[6];
    for (int i = 0; i < 6; i++) {
        W[i]  = (const float*)d_in[3 + 2 * i];
        bb[i] = (const float*)d_in[4 + 2 * i];
    }
    const int* smi = (const int*)d_in[15];
    const int* spi = (const int*)d_in[16];
    float* out = (float*)d_out;

    float *bufA, *bufB;
    cudaGetSymbolAddress((void**)&bufA, g_bufA);
    cudaGetSymbolAddress((void**)&bufB, g_bufB);

    build_csr_kernel<<<2, 256>>>(smi, smv, spi, spv);

    const int tpb = 256;
    const int mblk = M_ROWS / BM;  // 510

    // enc0 (2->400): SpMM-first on d=2, then fused elementwise layer
    spmm_d2_kernel<<<(M_ROWS + tpb - 1) / tpb, tpb>>>(0, H, bufA, 0);
    enc0_kernel<<<(M_ROWS * 100 + tpb - 1) / tpb, tpb>>>(bufA, W[0], bb[0], bufB);

    // enc1 (400->300): GEMM+bias, then SpMM+ReLU on d=300
    gemm_kernel<0><<<dim3(mblk, 3), 256>>>(bufB, W[1], bb[1], 0, bufA, 400, 300);
    spmm_kernel<<<dim3(N_NODES, BATCH), spmm_threads(300)>>>(0, bufA, bufB, 300, 1);

    // enc2 (300->100): GEMM+bias, then SpMM+ReLU on d=100
    gemm_kernel<0><<<dim3(mblk, 1), 256>>>(bufB, W[2], bb[2], 0, bufA, 300, 100);
    spmm_kernel<<<dim3(N_NODES, BATCH), spmm_threads(100)>>>(0, bufA, bufB, 100, 1);

    // dec0 (100->300): SpMM-first (sp) on d=100, fused epilogue GEMM
    spmm_kernel<<<dim3(N_NODES, BATCH), spmm_threads(100)>>>(1, bufB, bufA, 100, 0);
    gemm_kernel<1><<<dim3(mblk, 3), 256>>>(bufA, W[3], bb[3], 1, bufB, 100, 300);

    // dec1 (300->400): SpMM-first (sp) on d=300, fused epilogue GEMM
    spmm_kernel<<<dim3(N_NODES, BATCH), spmm_threads(300)>>>(1, bufB, bufA, 300, 0);
    gemm_kernel<1><<<dim3(mblk, 4), 256>>>(bufA, W[4], bb[4], 1, bufB, 300, 400);

    // dec2 (400->2): thin GEMM+bias, then SpMM+ReLU on d=2 into d_out
    gemm_thin_kernel<<<M_ROWS / 8, 256>>>(bufB, W[5], bb[5], bufA, 400);
    spmm_d2_kernel<<<(M_ROWS + tpb - 1) / tpb, tpb>>>(1, bufA, out, 1);
}

// round 8
// speedup vs baseline: 1.9641x; 1.9641x over previous
#include <cuda_runtime.h>
#include <cuda_bf16.h>
#include <cstdint>

#define N_NODES 255
#define NNZ_E   2550
#define BATCH   512
#define M_ROWS  (BATCH * N_NODES)   // 130560 (divisible by 128)
#define MAXD    400
#define MAXKPAD 448

// ---------------- device scratch (no allocations allowed) ----------------
__device__ float         g_bufA[M_ROWS * MAXD];
__device__ float         g_bufB[M_ROWS * MAXD];
__device__ __nv_bfloat16 g_hi[M_ROWS * MAXKPAD];
__device__ __nv_bfloat16 g_lo[M_ROWS * MAXKPAD];
__device__ __nv_bfloat16 g_wstack[520192];          // max Npad*3*Kpad = 516096
__device__ int   g_rowptr[2][N_NODES + 1];
__device__ int   g_cols[2][NNZ_E];
__device__ float g_vals[2][NNZ_E];
__device__ float g_rowsum[2][N_NODES];

// ================= PTX helpers =================
__device__ __forceinline__ uint32_t smem_u32(const void* p) {
    uint32_t a;
    asm("{ .reg .u64 t; cvta.to.shared.u64 t, %1; cvt.u32.u64 %0, t; }" : "=r"(a) : "l"(p));
    return a;
}
__device__ __forceinline__ void ldmx4(uint32_t& r0, uint32_t& r1, uint32_t& r2, uint32_t& r3,
                                      uint32_t addr) {
    asm volatile("ldmatrix.sync.aligned.m8n8.x4.shared.b16 {%0,%1,%2,%3}, [%4];"
                 : "=r"(r0), "=r"(r1), "=r"(r2), "=r"(r3) : "r"(addr));
}
__device__ __forceinline__ void mma16816(float* d, const uint32_t* a, const uint32_t* b) {
    asm volatile(
        "mma.sync.aligned.m16n8k16.row.col.f32.bf16.bf16.f32 "
        "{%0,%1,%2,%3}, {%4,%5,%6,%7}, {%8,%9}, {%0,%1,%2,%3};"
        : "+f"(d[0]), "+f"(d[1]), "+f"(d[2]), "+f"(d[3])
        : "r"(a[0]), "r"(a[1]), "r"(a[2]), "r"(a[3]), "r"(b[0]), "r"(b[1]));
}

// ---------------- deterministic COO -> CSR build (1 block per matrix) ----
__global__ void build_csr_kernel(const int* __restrict__ sm_idx, const float* __restrict__ sm_val,
                                 const int* __restrict__ sp_idx, const float* __restrict__ sp_val) {
    __shared__ int   srow[NNZ_E];
    __shared__ float sval[NNZ_E];
    __shared__ int   rptr[N_NODES + 1];
    __shared__ int   cnt[N_NODES];
    const int mat = blockIdx.x;
    const int*   idx = mat ? sp_idx : sm_idx;
    const float* val = mat ? sp_val : sm_val;
    const int t = threadIdx.x;

    for (int e = t; e < NNZ_E; e += blockDim.x) { srow[e] = idx[2 * e]; sval[e] = val[e]; }
    for (int i = t; i < N_NODES; i += blockDim.x) cnt[i] = 0;
    __syncthreads();
    for (int e = t; e < NNZ_E; e += blockDim.x) atomicAdd(&cnt[srow[e]], 1);
    __syncthreads();
    if (t == 0) {
        int s = 0;
        for (int i = 0; i < N_NODES; i++) { rptr[i] = s; s += cnt[i]; }
        rptr[N_NODES] = s;
    }
    __syncthreads();
    for (int e = t; e < NNZ_E; e += blockDim.x) {
        const int r = srow[e];
        int rank = 0;
        for (int e2 = 0; e2 < e; e2++) rank += (srow[e2] == r) ? 1 : 0;
        const int slot = rptr[r] + rank;
        g_cols[mat][slot] = idx[2 * e + 1];
        g_vals[mat][slot] = sval[e];
    }
    for (int i = t; i <= N_NODES; i += blockDim.x) g_rowptr[mat][i] = rptr[i];
    for (int i = t; i < N_NODES; i += blockDim.x) {
        float s = 0.f;
        for (int e = 0; e < NNZ_E; e++)
            if (srow[e] == i) s += sval[e];
        g_rowsum[mat][i] = s;
    }
}

// ---------------- SpMM, feature dim = 2 ----------------------------------
__global__ void spmm_d2_kernel(int mat, const float* __restrict__ X,
                               float* __restrict__ out, int relu) {
    const int t = blockIdx.x * blockDim.x + threadIdx.x;
    if (t >= M_ROWS) return;
    const int b = t / N_NODES;
    const int i = t - b * N_NODES;
    const int p0 = g_rowptr[mat][i], p1 = g_rowptr[mat][i + 1];
    const float2* Xb = reinterpret_cast<const float2*>(X) + (size_t)b * N_NODES;
    float a0 = 0.f, a1 = 0.f;
    for (int e = p0; e < p1; e++) {
        const float v = g_vals[mat][e];
        const float2 x = Xb[g_cols[mat][e]];
        a0 = fmaf(v, x.x, a0);
        a1 = fmaf(v, x.y, a1);
    }
    if (relu) { a0 = fmaxf(a0, 0.f); a1 = fmaxf(a1, 0.f); }
    reinterpret_cast<float2*>(out)[t] = make_float2(a0, a1);
}

// ---------------- SpMM, generic d, fp32 out ------------------------------
__global__ void spmm_kernel(int mat, const float* __restrict__ Z,
                            float* __restrict__ out, int d, int relu) {
    const int i = blockIdx.x, b = blockIdx.y;
    const int p0 = g_rowptr[mat][i], p1 = g_rowptr[mat][i + 1];
    const float* Zb = Z + (size_t)b * N_NODES * d;
    float* ob = out + ((size_t)b * N_NODES + i) * d;
    const int d4 = d >> 2;
    for (int q = threadIdx.x; q < d4; q += blockDim.x) {
        float4 acc = make_float4(0.f, 0.f, 0.f, 0.f);
        for (int e = p0; e < p1; e++) {
            const float v = g_vals[mat][e];
            const float4 z = *reinterpret_cast<const float4*>(Zb + g_cols[mat][e] * d + q * 4);
            acc.x = fmaf(v, z.x, acc.x);
            acc.y = fmaf(v, z.y, acc.y);
            acc.z = fmaf(v, z.z, acc.z);
            acc.w = fmaf(v, z.w, acc.w);
        }
        if (relu) {
            acc.x = fmaxf(acc.x, 0.f); acc.y = fmaxf(acc.y, 0.f);
            acc.z = fmaxf(acc.z, 0.f); acc.w = fmaxf(acc.w, 0.f);
        }
        *reinterpret_cast<float4*>(ob + q * 4) = acc;
    }
}

// ---------------- SpMM -> bf16 hi/lo (zero-padded to Kpad) ---------------
__device__ __forceinline__ void split_store(__nv_bfloat16* hi, __nv_bfloat16* lo,
                                            size_t off, float x) {
    const __nv_bfloat16 h = __float2bfloat16_rn(x);
    hi[off] = h;
    lo[off] = __float2bfloat16_rn(x - __bfloat162float(h));
}
__global__ void spmm_hilo_kernel(int mat, const float* __restrict__ Z,
                                 __nv_bfloat16* __restrict__ hi, __nv_bfloat16* __restrict__ lo,
                                 int d, int Kpad, int relu) {
    const int i = blockIdx.x, b = blockIdx.y;
    const int p0 = g_rowptr[mat][i], p1 = g_rowptr[mat][i + 1];
    const float* Zb = Z + (size_t)b * N_NODES * d;
    const size_t obase = ((size_t)b * N_NODES + i) * Kpad;
    const int kp4 = Kpad >> 2;
    for (int q = threadIdx.x; q < kp4; q += blockDim.x) {
        float4 acc = make_float4(0.f, 0.f, 0.f, 0.f);
        if (q * 4 < d) {
            for (int e = p0; e < p1; e++) {
                const float v = g_vals[mat][e];
                const float4 z = *reinterpret_cast<const float4*>(Zb + g_cols[mat][e] * d + q * 4);
                acc.x = fmaf(v, z.x, acc.x);
                acc.y = fmaf(v, z.y, acc.y);
                acc.z = fmaf(v, z.z, acc.z);
                acc.w = fmaf(v, z.w, acc.w);
            }
            if (relu) {
                acc.x = fmaxf(acc.x, 0.f); acc.y = fmaxf(acc.y, 0.f);
                acc.z = fmaxf(acc.z, 0.f); acc.w = fmaxf(acc.w, 0.f);
            }
        }
        split_store(hi, lo, obase + q * 4 + 0, acc.x);
        split_store(hi, lo, obase + q * 4 + 1, acc.y);
        split_store(hi, lo, obase + q * 4 + 2, acc.z);
        split_store(hi, lo, obase + q * 4 + 3, acc.w);
    }
}

// ---------------- enc0: relu(x0*W0 + x1*W1 + rowsum*b) -> hi/lo (Kpad=448)
__global__ void enc0_hilo_kernel(const float* __restrict__ X2, const float* __restrict__ W,
                                 const float* __restrict__ b,
                                 __nv_bfloat16* __restrict__ hi, __nv_bfloat16* __restrict__ lo) {
    const int idx = blockIdx.x * blockDim.x + threadIdx.x;  // M_ROWS * 112 float4-groups
    if (idx >= M_ROWS * 112) return;
    const int m = idx / 112;
    const int q = idx - m * 112;
    const size_t obase = (size_t)m * MAXKPAD + q * 4;
    if (q >= 100) {
        const __nv_bfloat16 z = __float2bfloat16_rn(0.f);
#pragma unroll
        for (int j = 0; j < 4; j++) { hi[obase + j] = z; lo[obase + j] = z; }
        return;
    }
    const float2 a = reinterpret_cast<const float2*>(X2)[m];
    const float4 w0 = reinterpret_cast<const float4*>(W)[q];
    const float4 w1 = reinterpret_cast<const float4*>(W + 400)[q];
    const float4 bv = reinterpret_cast<const float4*>(b)[q];
    const float sc = g_rowsum[0][m % N_NODES];
    float o[4];
    o[0] = fmaxf(fmaf(a.x, w0.x, fmaf(a.y, w1.x, sc * bv.x)), 0.f);
    o[1] = fmaxf(fmaf(a.x, w0.y, fmaf(a.y, w1.y, sc * bv.y)), 0.f);
    o[2] = fmaxf(fmaf(a.x, w0.z, fmaf(a.y, w1.z, sc * bv.z)), 0.f);
    o[3] = fmaxf(fmaf(a.x, w0.w, fmaf(a.y, w1.w, sc * bv.w)), 0.f);
#pragma unroll
    for (int j = 0; j < 4; j++) split_store(hi, lo, obase + j, o[j]);
}

// ---------------- weight prep: W[K,N] fp32 -> Wstack[Npad, 3*Kpad] bf16 --
// segments along k': [0,Kpad)=Whi^T, [Kpad,2Kpad)=Wlo^T, [2Kpad,3Kpad)=Whi^T
__global__ void prep_w_kernel(const float* __restrict__ W, int K, int N, int Kpad, int Npad) {
    const int t = blockIdx.x * blockDim.x + threadIdx.x;
    const int total = Npad * 3 * Kpad;
    if (t >= total) return;
    const int n = t / (3 * Kpad);
    const int kk = t - n * 3 * Kpad;
    const int seg = kk / Kpad;
    const int k = kk - seg * Kpad;
    float v = 0.f;
    if (n < N && k < K) v = W[(size_t)k * N + n];
    const __nv_bfloat16 h = __float2bfloat16_rn(v);
    g_wstack[t] = (seg == 1) ? __float2bfloat16_rn(v - __bfloat162float(h)) : h;
}

// ---------------- mma.sync bf16 GEMM (3-term fp32 emulation) -------------
// C[M,N] = act(A@W + scale*bias); A as hi/lo [M x Kpad], W stacked [Npad x 3Kpad].
// CTA 128x128, BK=32, 256 thr (warps 4x2 -> 32x64 warp tile), dbl-buffered.
#define ASTRIDE 80   // bytes per padded smem row (32 bf16 + 8 pad)

__global__ void __launch_bounds__(256, 2)
gemm_mma_kernel(const __nv_bfloat16* __restrict__ Ahi, const __nv_bfloat16* __restrict__ Alo,
                const __nv_bfloat16* __restrict__ Wst, const float* __restrict__ bias,
                int mat, int mode, float* __restrict__ C, int Kpad, int N) {
    __shared__ __align__(128) char smA[2][128 * ASTRIDE];
    __shared__ __align__(128) char smB[2][128 * ASTRIDE];

    const int tid = threadIdx.x;
    const int lane = tid & 31;
    const int w = tid >> 5;
    const int warpM = (w & 3) * 32;
    const int warpN = (w >> 2) * 64;
    const int mBase = blockIdx.x * 128;
    const int nBase = blockIdx.y * 128;

    float acc[2][8][4];
#pragma unroll
    for (int i = 0; i < 2; i++)
#pragma unroll
        for (int j = 0; j < 8; j++)
#pragma unroll
            for (int q = 0; q < 4; q++) acc[i][j][q] = 0.f;

    // ldmatrix per-lane offsets (bytes), ks=0
    const int arow = (lane & 7) + ((lane >> 3) & 1) * 8;
    const int acol = (lane >> 4) * 8;
    uint32_t aoff[2];
#pragma unroll
    for (int mt = 0; mt < 2; mt++)
        aoff[mt] = (uint32_t)((warpM + mt * 16 + arow) * ASTRIDE + acol * 2);
    const int bn = (lane >> 4) * 8 + (lane & 7);
    const int bk = ((lane >> 3) & 1) * 8;
    uint32_t boff[4];
#pragma unroll
    for (int j = 0; j < 4; j++)
        boff[j] = (uint32_t)((warpN + j * 16 + bn) * ASTRIDE + bk * 2);

    const uint32_t smAb[2] = { smem_u32(smA[0]), smem_u32(smA[1]) };
    const uint32_t smBb[2] = { smem_u32(smB[0]), smem_u32(smB[1]) };

    // gmem staging: per thread 2 x 16B for A and B; row = tid>>1, ch = 2*(tid&1)+q
    const int ldrow = tid >> 1;
    const int ch0 = (tid & 1) * 2;
    const uint32_t stoffA = (uint32_t)(ldrow * ASTRIDE + ch0 * 16);
    const int wrow = 3 * Kpad;
    const __nv_bfloat16* Brow = Wst + (size_t)(nBase + ldrow) * wrow;

    const int nch = Kpad >> 5;
    const int total = 3 * nch;

    uint4 sa[2], sb[2];
    // prefetch chunk 0 (phase 0: Ahi, seg 0)
    {
        const __nv_bfloat16* Ap = Ahi + (size_t)(mBase + ldrow) * Kpad;
#pragma unroll
        for (int q = 0; q < 2; q++) {
            sa[q] = *reinterpret_cast<const uint4*>(Ap + (ch0 + q) * 8);
            sb[q] = *reinterpret_cast<const uint4*>(Brow + (ch0 + q) * 8);
        }
    }
#pragma unroll
    for (int q = 0; q < 2; q++) {
        *reinterpret_cast<uint4*>(smA[0] + stoffA + q * 16) = sa[q];
        *reinterpret_cast<uint4*>(smB[0] + stoffA + q * 16) = sb[q];
    }
    __syncthreads();

    for (int c = 0; c < total; c++) {
        const int buf = c & 1;
        // prefetch next chunk
        if (c + 1 < total) {
            const int cn = c + 1;
            const int phase = cn / nch;
            const int kc = cn - phase * nch;
            const __nv_bfloat16* Ap = (phase == 2 ? Alo : Ahi) +
                                      (size_t)(mBase + ldrow) * Kpad + kc * 32;
            const __nv_bfloat16* Bp = Brow + phase * Kpad + kc * 32;
#pragma unroll
            for (int q = 0; q < 2; q++) {
                sa[q] = *reinterpret_cast<const uint4*>(Ap + (ch0 + q) * 8);
                sb[q] = *reinterpret_cast<const uint4*>(Bp + (ch0 + q) * 8);
            }
        }

        // compute on buf
#pragma unroll
        for (int ks = 0; ks < 2; ks++) {
            uint32_t af[2][4];
#pragma unroll
            for (int mt = 0; mt < 2; mt++)
                ldmx4(af[mt][0], af[mt][1], af[mt][2], af[mt][3],
                      smAb[buf] + aoff[mt] + ks * 32);
            uint32_t bf[8][2];
#pragma unroll
            for (int j = 0; j < 4; j++) {
                uint32_t r0, r1, r2, r3;
                ldmx4(r0, r1, r2, r3, smBb[buf] + boff[j] + ks * 32);
                bf[2 * j][0] = r0;     bf[2 * j][1] = r1;
                bf[2 * j + 1][0] = r2; bf[2 * j + 1][1] = r3;
            }
#pragma unroll
            for (int mt = 0; mt < 2; mt++)
#pragma unroll
                for (int nt = 0; nt < 8; nt++)
                    mma16816(acc[mt][nt], af[mt], bf[nt]);
        }

        if (c + 1 < total) {
            __syncthreads();
            const int bn2 = (c + 1) & 1;
#pragma unroll
            for (int q = 0; q < 2; q++) {
                *reinterpret_cast<uint4*>(smA[bn2] + stoffA + q * 16) = sa[q];
                *reinterpret_cast<uint4*>(smB[bn2] + stoffA + q * 16) = sb[q];
            }
            __syncthreads();
        }
    }

    // epilogue: c0/c1 at (row, n..n+1), c2/c3 at (row+8, n..n+1)
#pragma unroll
    for (int mt = 0; mt < 2; mt++) {
        const int r0 = mBase + warpM + mt * 16 + (lane >> 2);
        const int r1 = r0 + 8;
        const float s0 = (mode == 1) ? g_rowsum[mat][r0 % N_NODES] : 1.f;
        const float s1 = (mode == 1) ? g_rowsum[mat][r1 % N_NODES] : 1.f;
#pragma unroll
        for (int nt = 0; nt < 8; nt++) {
            const int n = nBase + warpN + nt * 8 + (lane & 3) * 2;
            if (n >= N) continue;
            const float b0 = bias[n] * 1.f, b1 = bias[n + 1];
            float o0 = acc[mt][nt][0] + b0 * s0;
            float o1 = acc[mt][nt][1] + b1 * s0;
            float o2 = acc[mt][nt][2] + b0 * s1;
            float o3 = acc[mt][nt][3] + b1 * s1;
            if (mode == 1) {
                o0 = fmaxf(o0, 0.f); o1 = fmaxf(o1, 0.f);
                o2 = fmaxf(o2, 0.f); o3 = fmaxf(o3, 0.f);
            }
            *reinterpret_cast<float2*>(C + (size_t)r0 * N + n) = make_float2(o0, o1);
            *reinterpret_cast<float2*>(C + (size_t)r1 * N + n) = make_float2(o2, o3);
        }
    }
}

// ---------------- thin GEMM for N=2 (dec2): warp per row -----------------
__global__ void gemm_thin_kernel(const float* __restrict__ X, const float* __restrict__ Wt,
                                 const float* __restrict__ bias, float* __restrict__ out, int K) {
    __shared__ float Ws[2 * MAXD];
    for (int i = threadIdx.x; i < 2 * K; i += blockDim.x) Ws[i] = Wt[i];
    __syncthreads();
    const int warp = threadIdx.x >> 5, lane = threadIdx.x & 31;
    const int row = blockIdx.x * 8 + warp;
    if (row >= M_ROWS) return;
    const float* x = X + (size_t)row * K;
    float a0 = 0.f, a1 = 0.f;
    for (int k = lane; k < K; k += 32) {
        const float xv = x[k];
        a0 = fmaf(xv, Ws[2 * k], a0);
        a1 = fmaf(xv, Ws[2 * k + 1], a1);
    }
#pragma unroll
    for (int off = 16; off; off >>= 1) {
        a0 += __shfl_down_sync(0xffffffffu, a0, off);
        a1 += __shfl_down_sync(0xffffffffu, a1, off);
    }
    if (lane == 0) {
        out[2 * row]     = a0 + bias[0];
        out[2 * row + 1] = a1 + bias[1];
    }
}

// ---------------- launch -------------------------------------------------
static inline int clamp_threads(int work) {
    int t = (work + 31) & ~31;
    if (t < 32) t = 32;
    if (t > 128) t = 128;
    return t;
}

extern "C" void kernel_launch(void* const* d_in, const int* in_sizes, int n_in,
                              void* d_out, int out_size) {
    const float* H   = (const float*)d_in[0];
    const float* smv = (const float*)d_in[1];
    const float* spv = (const float*)d_in[2];
    const float* W[6];
    const float* bb[6];
    for (int i = 0; i < 6; i++) {
        W[i]  = (const float*)d_in[3 + 2 * i];
        bb[i] = (const float*)d_in[4 + 2 * i];
    }
    const int* smi = (const int*)d_in[15];
    const int* spi = (const int*)d_in[16];
    float* out = (float*)d_out;

    float *bufA, *bufB;
    __nv_bfloat16 *hi, *lo, *wst;
    cudaGetSymbolAddress((void**)&bufA, g_bufA);
    cudaGetSymbolAddress((void**)&bufB, g_bufB);
    cudaGetSymbolAddress((void**)&hi, g_hi);
    cudaGetSymbolAddress((void**)&lo, g_lo);
    cudaGetSymbolAddress((void**)&wst, g_wstack);

    const int tpb = 256;
    const int mblk = M_ROWS / 128;  // 1020

    build_csr_kernel<<<2, 256>>>(smi, smv, spi, spv);

    // enc0 (2->400): SpMM(sm) on d=2, fused layer -> hi/lo (Kpad=448)
    spmm_d2_kernel<<<(M_ROWS + tpb - 1) / tpb, tpb>>>(0, H, bufA, 0);
    enc0_hilo_kernel<<<(M_ROWS * 112 + tpb - 1) / tpb, tpb>>>(bufA, W[0], bb[0], hi, lo);

    // enc1 (400->300), Kpad=448, Npad=384
    prep_w_kernel<<<(384 * 3 * 448 + tpb - 1) / tpb, tpb>>>(W[1], 400, 300, 448, 384);
    gemm_mma_kernel<<<dim3(mblk, 3), 256>>>(hi, lo, wst, bb[1], 0, 0, bufB, 448, 300);
    spmm_hilo_kernel<<<dim3(N_NODES, BATCH), clamp_threads(320 / 4)>>>(0, bufB, hi, lo, 300, 320, 1);

    // enc2 (300->100), Kpad=320, Npad=128
    prep_w_kernel<<<(128 * 3 * 320 + tpb - 1) / tpb, tpb>>>(W[2], 300, 100, 320, 128);
    gemm_mma_kernel<<<dim3(mblk, 1), 256>>>(hi, lo, wst, bb[2], 0, 0, bufA, 320, 100);
    spmm_kernel<<<dim3(N_NODES, BATCH), clamp_threads(100 / 4)>>>(0, bufA, bufB, 100, 1);

    // dec0 (100->300): SpMM(sp)-first -> hi/lo (Kpad=128); GEMM mode1
    spmm_hilo_kernel<<<dim3(N_NODES, BATCH), clamp_threads(128 / 4)>>>(1, bufB, hi, lo, 100, 128, 0);
    prep_w_kernel<<<(384 * 3 * 128 + tpb - 1) / tpb, tpb>>>(W[3], 100, 300, 128, 384);
    gemm_mma_kernel<<<dim3(mblk, 3), 256>>>(hi, lo, wst, bb[3], 1, 1, bufA, 128, 300);

    // dec1 (300->400): SpMM(sp)-first -> hi/lo (Kpad=320); GEMM mode1
    spmm_hilo_kernel<<<dim3(N_NODES, BATCH), clamp_threads(320 / 4)>>>(1, bufA, hi, lo, 300, 320, 0);
    prep_w_kernel<<<(512 * 3 * 320 + tpb - 1) / tpb, tpb>>>(W[4], 300, 400, 320, 512);
    gemm_mma_kernel<<<dim3(mblk, 4), 256>>>(hi, lo, wst, bb[4], 1, 1, bufB, 320, 400);

    // dec2 (400->2): thin GEMM+bias, then SpMM(sp)+ReLU on d=2 into d_out
    gemm_thin_kernel<<<M_ROWS / 8, 256>>>(bufB, W[5], bb[5], bufA, 400);
    spmm_d2_kernel<<<(M_ROWS + tpb - 1) / tpb, tpb>>>(1, bufA, out, 1);
}